// round 13
// baseline (speedup 1.0000x reference)
#include <cuda_runtime.h>

#define DD 24
#define HH 48
#define WW 64
#define NV (DD*HH*WW)        /* 73728 interior voxels */
#define CIN 32
#define COUT 48
#define OSPLIT 16            /* channels per qkv block (gridDim.y = 3) */

#define TD 4
#define TH 8
#define SROW 68                        /* padded smem row stride (floats) */
#define NROWS ((TD+2)*(TH+2))          /* 60 */

// scratch (allocation-free rule: __device__ globals)
__device__ float g_q[COUT * NV];
__device__ float g_k[COUT * NV];
__device__ float g_v[COUT * NV];

typedef unsigned long long u64;
__device__ __forceinline__ u64 fma2(u64 a, u64 b, u64 c) {
    u64 d; asm("fma.rn.f32x2 %0,%1,%2,%3;" : "=l"(d) : "l"(a), "l"(b), "l"(c));
    return d;
}
__device__ __forceinline__ u64 add2(u64 a, u64 b) {
    u64 d; asm("add.rn.f32x2 %0,%1,%2;" : "=l"(d) : "l"(a), "l"(b));
    return d;
}
__device__ __forceinline__ float ex2f(float x) {
    float y; asm("ex2.approx.ftz.f32 %0, %1;" : "=f"(y) : "f"(x)); return y;
}
__device__ __forceinline__ float rcpf(float x) {
    float y; asm("rcp.approx.ftz.f32 %0, %1;" : "=f"(y) : "f"(x)); return y;
}

// ---------------------------------------------------------------------------
// Fused QKV: one thread = one voxel pair x 16 channels (gridDim.y = 3 picks
// the channel third). Packed f32x2 math, LDS.128 weights, unroll 4.
// 128-thread blocks: ~96 regs -> 5 blocks/SM -> ~20 warps/SM (was 16),
// and 864 blocks keep all SMs at full residency.
// ---------------------------------------------------------------------------
__global__ __launch_bounds__(128)
void qkv_kernel(const float* __restrict__ x,
                const float* __restrict__ Wq,
                const float* __restrict__ Wk,
                const float* __restrict__ Wv) {
    __shared__ u64 swq[OSPLIT * CIN];
    __shared__ u64 swk[OSPLIT * CIN];
    __shared__ u64 swv[OSPLIT * CIN];

    const int ob = blockIdx.y * OSPLIT;
    for (int i = threadIdx.x; i < OSPLIT * CIN; i += 128) {
        const int gi = ob * CIN + i;
        float a = Wq[gi], b = Wk[gi], c = Wv[gi];
        u64 pa, pb, pc;
        asm("mov.b64 %0,{%1,%1};" : "=l"(pa) : "f"(a));
        asm("mov.b64 %0,{%1,%1};" : "=l"(pb) : "f"(b));
        asm("mov.b64 %0,{%1,%1};" : "=l"(pc) : "f"(c));
        swq[i] = pa; swk[i] = pb; swv[i] = pc;
    }
    __syncthreads();

    const int t = blockIdx.x * 128 + threadIdx.x;   // 0..36863
    const int v0 = t * 2;

    u64 xs[CIN];
    #pragma unroll
    for (int c = 0; c < CIN; c++)
        xs[c] = *(const u64*)(x + c * NV + v0);

    float* __restrict__ gq = g_q + ob * NV + v0;
    float* __restrict__ gk = g_k + ob * NV + v0;
    float* __restrict__ gv = g_v + ob * NV + v0;

    #pragma unroll 4
    for (int o = 0; o < OSPLIT; o++) {
        u64 qa = 0, qb = 0, ka = 0, kb = 0, va = 0, vb = 0;
        #pragma unroll
        for (int c = 0; c < CIN; c += 2) {
            const u64 x0 = xs[c], x1 = xs[c + 1];
            const ulonglong2 wq = *(const ulonglong2*)&swq[o * CIN + c];
            const ulonglong2 wk = *(const ulonglong2*)&swk[o * CIN + c];
            const ulonglong2 wv = *(const ulonglong2*)&swv[o * CIN + c];
            qa = fma2(wq.x, x0, qa);  qb = fma2(wq.y, x1, qb);
            ka = fma2(wk.x, x0, ka);  kb = fma2(wk.y, x1, kb);
            va = fma2(wv.x, x0, va);  vb = fma2(wv.y, x1, vb);
        }
        *(u64*)(gq + o * NV) = add2(qa, qb);
        *(u64*)(gk + o * NV) = add2(ka, kb);
        *(u64*)(gv + o * NV) = add2(va, vb);
    }
}

// ---------------------------------------------------------------------------
// Pass 2 (exact R10-measured 32.0us version): per-channel attention,
// 4 outputs/thread, tile 4x8x64 (512 threads); div-free LDG.128 halo load.
// ---------------------------------------------------------------------------
template<int GRP>
__device__ __forceinline__ void attn_core(const float* __restrict__ sk,
                                          const float* __restrict__ sv,
                                          const float qs[4],
                                          const float qb[3][4],
                                          int rbase, int w0,
                                          float num[4], float den[4]) {
    #pragma unroll
    for (int kd = 0; kd < 3; kd++) {
        #pragma unroll
        for (int kh = 0; kh < 3; kh++) {
            const int rb = rbase + (kd * (TH + 2) + kh) * SROW + w0;
            const float4 ka = *(const float4*)(sk + rb);
            const float2 kc = *(const float2*)(sk + rb + 4);
            const float4 va = *(const float4*)(sv + rb);
            const float2 vc = *(const float2*)(sv + rb + 4);
            const float kk[6] = {ka.x, ka.y, ka.z, ka.w, kc.x, kc.y};
            const float vv[6] = {va.x, va.y, va.z, va.w, vc.x, vc.y};
            #pragma unroll
            for (int kw = 0; kw < 3; kw++) {
                const int sel = (GRP == 0) ? kw : ((GRP == 1) ? kd : kh);
                #pragma unroll
                for (int wi = 0; wi < 4; wi++) {
                    const float arg = fmaf(qs[wi], kk[wi + kw], qb[sel][wi]);
                    const float ex  = ex2f(arg);
                    den[wi] += ex;
                    num[wi] = fmaf(ex, vv[wi + kw], num[wi]);
                }
            }
        }
    }
}

__global__ __launch_bounds__(512, 3)
void attn_kernel(const float* __restrict__ rel_h,
                 const float* __restrict__ rel_w,
                 const float* __restrict__ rel_d,
                 float* __restrict__ out) {
    __shared__ float sk[NROWS * SROW];
    __shared__ float sv[NROWS * SROW];

    const int o  = blockIdx.z;
    const int d0 = blockIdx.x * TD;
    const int h0 = blockIdx.y * TH;
    const int tid = threadIdx.x + (threadIdx.y << 4) + (threadIdx.z << 7);

    // ---- hoisted gmem loads (overlap with halo fill) ----
    const int w0 = threadIdx.x << 2;
    const int hl = threadIdx.y;
    const int dl = threadIdx.z;
    const int vox0 = ((d0 + dl) * HH + (h0 + hl)) * WW + w0;

    const float4 q4 = *(const float4*)(g_q + o * NV + vox0);
    const int grp = o >> 4, ci = o & 15;
    const float* rel = (grp == 0) ? (rel_d + ci * 3)
                     : (grp == 1) ? (rel_h + ci * 3)
                                  : (rel_w + ci * 3);
    const float b0 = rel[0], b1 = rel[1], b2 = rel[2];

    const float L2E = 1.4426950408889634f;
    float qs[4] = {q4.x * L2E, q4.y * L2E, q4.z * L2E, q4.w * L2E};
    float qb[3][4];
    #pragma unroll
    for (int wi = 0; wi < 4; wi++) {
        qb[0][wi] = qs[wi] * b0;
        qb[1][wi] = qs[wi] * b1;
        qb[2][wi] = qs[wi] * b2;
    }

    // ---- halo load ----
    // w-halo (smem cols 0 and 65) is globally out-of-bounds: always zero.
    if (tid < NROWS * 2) {
        const int r = tid >> 1;
        const int c = (tid & 1) ? 65 : 0;
        sk[r * SROW + c] = 0.f;
        sv[r * SROW + c] = 0.f;
    }
    // main region: row r (0..59), 64 floats per row, aligned LDG.128.
    {
        const int cbase = o * NV;
        const int cx = (tid & 15) << 2;     // w = cx..cx+3
        const int ry = tid >> 4;            // 0..31
        #pragma unroll
        for (int rr = 0; rr < 2; rr++) {
            const int r = ry + rr * 32;
            if (r < NROWS) {
                const int dd = r / (TH + 2);              // mul-shift
                const int hh = r - dd * (TH + 2);
                const int d = d0 + dd - 1;
                const int h = h0 + hh - 1;
                float4 kq = {0.f, 0.f, 0.f, 0.f};
                float4 vq = {0.f, 0.f, 0.f, 0.f};
                if (((unsigned)d < DD) & ((unsigned)h < HH)) {
                    const int g = cbase + (d * HH + h) * WW + cx;
                    kq = *(const float4*)(g_k + g);
                    vq = *(const float4*)(g_v + g);
                }
                const int s = r * SROW + 1 + cx;
                sk[s + 0] = kq.x; sk[s + 1] = kq.y; sk[s + 2] = kq.z; sk[s + 3] = kq.w;
                sv[s + 0] = vq.x; sv[s + 1] = vq.y; sv[s + 2] = vq.z; sv[s + 3] = vq.w;
            }
        }
    }
    __syncthreads();

    const int rbase = (dl * (TH + 2) + hl) * SROW;

    float num[4] = {0.f, 0.f, 0.f, 0.f};
    float den[4] = {0.f, 0.f, 0.f, 0.f};

    if (grp == 0)      attn_core<0>(sk, sv, qs, qb, rbase, w0, num, den);
    else if (grp == 1) attn_core<1>(sk, sv, qs, qb, rbase, w0, num, den);
    else               attn_core<2>(sk, sv, qs, qb, rbase, w0, num, den);

    float4 r;
    r.x = num[0] * rcpf(den[0]);
    r.y = num[1] * rcpf(den[1]);
    r.z = num[2] * rcpf(den[2]);
    r.w = num[3] * rcpf(den[3]);
    *(float4*)(out + o * NV + vox0) = r;
}

extern "C" void kernel_launch(void* const* d_in, const int* in_sizes, int n_in,
                              void* d_out, int out_size) {
    const float* x     = (const float*)d_in[0];
    const float* Wq    = (const float*)d_in[1];
    const float* Wk    = (const float*)d_in[2];
    const float* Wv    = (const float*)d_in[3];
    const float* rel_h = (const float*)d_in[4];
    const float* rel_w = (const float*)d_in[5];
    const float* rel_d = (const float*)d_in[6];
    float* out = (float*)d_out;

    dim3 g1(NV / 2 / 128, 3);
    qkv_kernel<<<g1, 128>>>(x, Wq, Wk, Wv);

    dim3 g2(DD / TD, HH / TH, COUT);
    dim3 b2(16, TH, TD);
    attn_kernel<<<g2, b2>>>(rel_h, rel_w, rel_d, out);
}

// round 14
// speedup vs baseline: 1.2532x; 1.2532x over previous
#include <cuda_runtime.h>

#define DD 24
#define HH 48
#define WW 64
#define NV (DD*HH*WW)        /* 73728 interior voxels */
#define CIN 32
#define COUT 48
#define OHALF 24             /* channels per qkv block (gridDim.y = 2) */

#define TD 4
#define TH 8
#define SROW 68                        /* padded smem row stride (floats) */
#define NROWS ((TD+2)*(TH+2))          /* 60 */

// scratch (allocation-free rule: __device__ globals)
__device__ float g_q[COUT * NV];
__device__ float g_k[COUT * NV];
__device__ float g_v[COUT * NV];

__device__ __forceinline__ float ex2f(float x) {
    float y; asm("ex2.approx.ftz.f32 %0, %1;" : "=f"(y) : "f"(x)); return y;
}
__device__ __forceinline__ float rcpf(float x) {
    float y; asm("rcp.approx.ftz.f32 %0, %1;" : "=f"(y) : "f"(x)); return y;
}

// ---------------------------------------------------------------------------
// Fused QKV, SCALAR form: one thread = one voxel x 24 channels (gridDim.y=2).
// xs[32] scalar regs (~55 regs total -> 4 blocks/SM -> 32 warps/SM; the
// f32x2 variant's 64-reg xs capped residency at 16 warps and ran at 45% of
// its issue floor). 2-way even/odd split accumulators match the f32x2
// pair-lane arithmetic exactly.
// ---------------------------------------------------------------------------
__global__ __launch_bounds__(256)
void qkv_kernel(const float* __restrict__ x,
                const float* __restrict__ Wq,
                const float* __restrict__ Wk,
                const float* __restrict__ Wv) {
    __shared__ float swq[OHALF * CIN];
    __shared__ float swk[OHALF * CIN];
    __shared__ float swv[OHALF * CIN];

    const int ob = blockIdx.y * OHALF;
    for (int i = threadIdx.x; i < OHALF * CIN; i += 256) {
        const int gi = ob * CIN + i;
        swq[i] = Wq[gi];
        swk[i] = Wk[gi];
        swv[i] = Wv[gi];
    }
    __syncthreads();

    const int v = blockIdx.x * 256 + threadIdx.x;   // 0..NV-1

    float xs[CIN];
    #pragma unroll
    for (int c = 0; c < CIN; c++)
        xs[c] = x[c * NV + v];

    float* __restrict__ gq = g_q + ob * NV + v;
    float* __restrict__ gk = g_k + ob * NV + v;
    float* __restrict__ gv = g_v + ob * NV + v;

    #pragma unroll 4
    for (int o = 0; o < OHALF; o++) {
        float q0 = 0.f, q1 = 0.f, k0 = 0.f, k1 = 0.f, p0 = 0.f, p1 = 0.f;
        #pragma unroll
        for (int c = 0; c < CIN; c += 4) {
            const float4 wq = *(const float4*)&swq[o * CIN + c];
            const float4 wk = *(const float4*)&swk[o * CIN + c];
            const float4 wv = *(const float4*)&swv[o * CIN + c];
            q0 = fmaf(wq.x, xs[c + 0], q0);  q1 = fmaf(wq.y, xs[c + 1], q1);
            q0 = fmaf(wq.z, xs[c + 2], q0);  q1 = fmaf(wq.w, xs[c + 3], q1);
            k0 = fmaf(wk.x, xs[c + 0], k0);  k1 = fmaf(wk.y, xs[c + 1], k1);
            k0 = fmaf(wk.z, xs[c + 2], k0);  k1 = fmaf(wk.w, xs[c + 3], k1);
            p0 = fmaf(wv.x, xs[c + 0], p0);  p1 = fmaf(wv.y, xs[c + 1], p1);
            p0 = fmaf(wv.z, xs[c + 2], p0);  p1 = fmaf(wv.w, xs[c + 3], p1);
        }
        gq[o * NV] = q0 + q1;
        gk[o * NV] = k0 + k1;
        gv[o * NV] = p0 + p1;
    }
}

// ---------------------------------------------------------------------------
// Pass 2 (exact R10-measured 32.0us version): per-channel attention,
// 4 outputs/thread, tile 4x8x64 (512 threads); div-free LDG.128 halo load.
// ---------------------------------------------------------------------------
template<int GRP>
__device__ __forceinline__ void attn_core(const float* __restrict__ sk,
                                          const float* __restrict__ sv,
                                          const float qs[4],
                                          const float qb[3][4],
                                          int rbase, int w0,
                                          float num[4], float den[4]) {
    #pragma unroll
    for (int kd = 0; kd < 3; kd++) {
        #pragma unroll
        for (int kh = 0; kh < 3; kh++) {
            const int rb = rbase + (kd * (TH + 2) + kh) * SROW + w0;
            const float4 ka = *(const float4*)(sk + rb);
            const float2 kc = *(const float2*)(sk + rb + 4);
            const float4 va = *(const float4*)(sv + rb);
            const float2 vc = *(const float2*)(sv + rb + 4);
            const float kk[6] = {ka.x, ka.y, ka.z, ka.w, kc.x, kc.y};
            const float vv[6] = {va.x, va.y, va.z, va.w, vc.x, vc.y};
            #pragma unroll
            for (int kw = 0; kw < 3; kw++) {
                const int sel = (GRP == 0) ? kw : ((GRP == 1) ? kd : kh);
                #pragma unroll
                for (int wi = 0; wi < 4; wi++) {
                    const float arg = fmaf(qs[wi], kk[wi + kw], qb[sel][wi]);
                    const float ex  = ex2f(arg);
                    den[wi] += ex;
                    num[wi] = fmaf(ex, vv[wi + kw], num[wi]);
                }
            }
        }
    }
}

__global__ __launch_bounds__(512, 3)
void attn_kernel(const float* __restrict__ rel_h,
                 const float* __restrict__ rel_w,
                 const float* __restrict__ rel_d,
                 float* __restrict__ out) {
    __shared__ float sk[NROWS * SROW];
    __shared__ float sv[NROWS * SROW];

    const int o  = blockIdx.z;
    const int d0 = blockIdx.x * TD;
    const int h0 = blockIdx.y * TH;
    const int tid = threadIdx.x + (threadIdx.y << 4) + (threadIdx.z << 7);

    // ---- hoisted gmem loads (overlap with halo fill) ----
    const int w0 = threadIdx.x << 2;
    const int hl = threadIdx.y;
    const int dl = threadIdx.z;
    const int vox0 = ((d0 + dl) * HH + (h0 + hl)) * WW + w0;

    const float4 q4 = *(const float4*)(g_q + o * NV + vox0);
    const int grp = o >> 4, ci = o & 15;
    const float* rel = (grp == 0) ? (rel_d + ci * 3)
                     : (grp == 1) ? (rel_h + ci * 3)
                                  : (rel_w + ci * 3);
    const float b0 = rel[0], b1 = rel[1], b2 = rel[2];

    const float L2E = 1.4426950408889634f;
    float qs[4] = {q4.x * L2E, q4.y * L2E, q4.z * L2E, q4.w * L2E};
    float qb[3][4];
    #pragma unroll
    for (int wi = 0; wi < 4; wi++) {
        qb[0][wi] = qs[wi] * b0;
        qb[1][wi] = qs[wi] * b1;
        qb[2][wi] = qs[wi] * b2;
    }

    // ---- halo load ----
    // w-halo (smem cols 0 and 65) is globally out-of-bounds: always zero.
    if (tid < NROWS * 2) {
        const int r = tid >> 1;
        const int c = (tid & 1) ? 65 : 0;
        sk[r * SROW + c] = 0.f;
        sv[r * SROW + c] = 0.f;
    }
    // main region: row r (0..59), 64 floats per row, aligned LDG.128.
    {
        const int cbase = o * NV;
        const int cx = (tid & 15) << 2;     // w = cx..cx+3
        const int ry = tid >> 4;            // 0..31
        #pragma unroll
        for (int rr = 0; rr < 2; rr++) {
            const int r = ry + rr * 32;
            if (r < NROWS) {
                const int dd = r / (TH + 2);              // mul-shift
                const int hh = r - dd * (TH + 2);
                const int d = d0 + dd - 1;
                const int h = h0 + hh - 1;
                float4 kq = {0.f, 0.f, 0.f, 0.f};
                float4 vq = {0.f, 0.f, 0.f, 0.f};
                if (((unsigned)d < DD) & ((unsigned)h < HH)) {
                    const int g = cbase + (d * HH + h) * WW + cx;
                    kq = *(const float4*)(g_k + g);
                    vq = *(const float4*)(g_v + g);
                }
                const int s = r * SROW + 1 + cx;
                sk[s + 0] = kq.x; sk[s + 1] = kq.y; sk[s + 2] = kq.z; sk[s + 3] = kq.w;
                sv[s + 0] = vq.x; sv[s + 1] = vq.y; sv[s + 2] = vq.z; sv[s + 3] = vq.w;
            }
        }
    }
    __syncthreads();

    const int rbase = (dl * (TH + 2) + hl) * SROW;

    float num[4] = {0.f, 0.f, 0.f, 0.f};
    float den[4] = {0.f, 0.f, 0.f, 0.f};

    if (grp == 0)      attn_core<0>(sk, sv, qs, qb, rbase, w0, num, den);
    else if (grp == 1) attn_core<1>(sk, sv, qs, qb, rbase, w0, num, den);
    else               attn_core<2>(sk, sv, qs, qb, rbase, w0, num, den);

    float4 r;
    r.x = num[0] * rcpf(den[0]);
    r.y = num[1] * rcpf(den[1]);
    r.z = num[2] * rcpf(den[2]);
    r.w = num[3] * rcpf(den[3]);
    *(float4*)(out + o * NV + vox0) = r;
}

extern "C" void kernel_launch(void* const* d_in, const int* in_sizes, int n_in,
                              void* d_out, int out_size) {
    const float* x     = (const float*)d_in[0];
    const float* Wq    = (const float*)d_in[1];
    const float* Wk    = (const float*)d_in[2];
    const float* Wv    = (const float*)d_in[3];
    const float* rel_h = (const float*)d_in[4];
    const float* rel_w = (const float*)d_in[5];
    const float* rel_d = (const float*)d_in[6];
    float* out = (float*)d_out;

    dim3 g1(NV / 256, 2);
    qkv_kernel<<<g1, 256>>>(x, Wq, Wk, Wv);

    dim3 g2(DD / TD, HH / TH, COUT);
    dim3 b2(16, TH, TD);
    attn_kernel<<<g2, b2>>>(rel_h, rel_w, rel_d, out);
}

// round 16
// speedup vs baseline: 1.4796x; 1.1807x over previous
#include <cuda_runtime.h>
#include <cuda_bf16.h>
#include <cstdint>

#define DD 24
#define HH 48
#define WW 64
#define NV (DD*HH*WW)        /* 73728 interior voxels */
#define CIN 32
#define COUT 48

#define TD 4
#define TH 8
#define SROW 68                        /* padded smem row stride (floats) */
#define NROWS ((TD+2)*(TH+2))          /* 60 */

// scratch (allocation-free rule: __device__ globals)
__device__ float g_q[COUT * NV];
__device__ float g_k[COUT * NV];
__device__ float g_v[COUT * NV];

__device__ __forceinline__ float ex2f(float x) {
    float y; asm("ex2.approx.ftz.f32 %0, %1;" : "=f"(y) : "f"(x)); return y;
}
__device__ __forceinline__ float rcpf(float x) {
    float y; asm("rcp.approx.ftz.f32 %0, %1;" : "=f"(y) : "f"(x)); return y;
}

// ---------------------------------------------------------------------------
// QKV via legacy tensor-core MMA (sm_100-safe HMMA path):
// D[128 vox, 144 ch] = x_tile(128x32) . W^T, split-bf16 (AhBh+AhBl+AlBh,
// fp32 accum -> fp32-class accuracy). 576 blocks x 256 threads (8 warps).
//
// smem row stride = 40 bf16 (20 words): every fragment register is ONE
// aligned 32-bit LDS and all 32 lanes hit distinct banks (grp*20+qd spans
// 0..31 mod 32).
// ---------------------------------------------------------------------------
#define XW 40   /* bf16 elems per smem row */

__device__ __forceinline__ void mma16816(float& c0, float& c1, float& c2, float& c3,
                                         uint32_t a0, uint32_t a1, uint32_t a2, uint32_t a3,
                                         uint32_t b0, uint32_t b1) {
    asm volatile(
        "mma.sync.aligned.m16n8k16.row.col.f32.bf16.bf16.f32 "
        "{%0,%1,%2,%3}, {%4,%5,%6,%7}, {%8,%9}, {%0,%1,%2,%3};"
        : "+f"(c0), "+f"(c1), "+f"(c2), "+f"(c3)
        : "r"(a0), "r"(a1), "r"(a2), "r"(a3), "r"(b0), "r"(b1));
}

__global__ __launch_bounds__(256)
void qkv_mma_kernel(const float* __restrict__ x,
                    const float* __restrict__ Wq,
                    const float* __restrict__ Wk,
                    const float* __restrict__ Wv) {
    __shared__ __nv_bfloat16 sxh[128 * XW];
    __shared__ __nv_bfloat16 sxl[128 * XW];
    __shared__ __nv_bfloat16 swh[144 * XW];
    __shared__ __nv_bfloat16 swl[144 * XW];

    const int t  = threadIdx.x;
    const int v0 = blockIdx.x * 128;

    // ---- stage x tile (coalesced per channel-row) ----
    #pragma unroll
    for (int i = 0; i < 16; i++) {
        const int idx = t + i * 256;           // 0..4095
        const int c  = idx >> 7;
        const int vl = idx & 127;
        const float a = x[c * NV + v0 + vl];
        const __nv_bfloat16 h = __float2bfloat16(a);
        const float r = a - __bfloat162float(h);
        sxh[vl * XW + c] = h;
        sxl[vl * XW + c] = __float2bfloat16(r);
    }
    // ---- stage W (144 rows: q 0..47 | k 48..95 | v 96..143) ----
    #pragma unroll
    for (int i = 0; i < 18; i++) {
        const int idx = t + i * 256;           // 0..4607
        const int rrow = idx >> 5;
        const int c    = idx & 31;
        const float* wsrc = (rrow < 48) ? (Wq + rrow * CIN)
                          : (rrow < 96) ? (Wk + (rrow - 48) * CIN)
                                        : (Wv + (rrow - 96) * CIN);
        const float a = wsrc[c];
        const __nv_bfloat16 h = __float2bfloat16(a);
        const float r = a - __bfloat162float(h);
        swh[rrow * XW + c] = h;
        swl[rrow * XW + c] = __float2bfloat16(r);
    }
    __syncthreads();

    const int lane = t & 31;
    const int wid  = t >> 5;
    const int grp  = lane >> 2;     // 0..7
    const int qd   = lane & 3;      // 0..3
    const int vr   = wid * 16 + grp;         // voxel row in tile (plus +8)
    const int v    = v0 + vr;

    // A fragments (hi and lo), both k-steps; each reg = one aligned LDS.32
    uint32_t ah[2][4], al[2][4];
    #pragma unroll
    for (int ks = 0; ks < 2; ks++) {
        const int cb = qd * 2 + ks * 16;
        ah[ks][0] = *(const uint32_t*)&sxh[(vr)     * XW + cb];
        ah[ks][1] = *(const uint32_t*)&sxh[(vr + 8) * XW + cb];
        ah[ks][2] = *(const uint32_t*)&sxh[(vr)     * XW + cb + 8];
        ah[ks][3] = *(const uint32_t*)&sxh[(vr + 8) * XW + cb + 8];
        al[ks][0] = *(const uint32_t*)&sxl[(vr)     * XW + cb];
        al[ks][1] = *(const uint32_t*)&sxl[(vr + 8) * XW + cb];
        al[ks][2] = *(const uint32_t*)&sxl[(vr)     * XW + cb + 8];
        al[ks][3] = *(const uint32_t*)&sxl[(vr + 8) * XW + cb + 8];
    }

    // 18 n8-tiles over the 144 stacked channels; store each tile immediately.
    #pragma unroll
    for (int nt = 0; nt < 18; nt++) {
        float c0 = 0.f, c1 = 0.f, c2 = 0.f, c3 = 0.f;
        const int nrow = nt * 8 + grp;
        #pragma unroll
        for (int ks = 0; ks < 2; ks++) {
            const int kb = qd * 2 + ks * 16;
            const uint32_t bh0 = *(const uint32_t*)&swh[nrow * XW + kb];
            const uint32_t bh1 = *(const uint32_t*)&swh[nrow * XW + kb + 8];
            const uint32_t bl0 = *(const uint32_t*)&swl[nrow * XW + kb];
            const uint32_t bl1 = *(const uint32_t*)&swl[nrow * XW + kb + 8];
            mma16816(c0, c1, c2, c3, ah[ks][0], ah[ks][1], ah[ks][2], ah[ks][3], bh0, bh1);
            mma16816(c0, c1, c2, c3, ah[ks][0], ah[ks][1], ah[ks][2], ah[ks][3], bl0, bl1);
            mma16816(c0, c1, c2, c3, al[ks][0], al[ks][1], al[ks][2], al[ks][3], bh0, bh1);
        }
        // C layout: (c0,c1) rows grp, cols qd*2,qd*2+1 ; (c2,c3) rows grp+8
        const int ch = nt * 8 + qd * 2;      // even; ch & ch+1 in same segment
        float* d0 = (ch < 48) ? (g_q + ch * NV)
                  : (ch < 96) ? (g_k + (ch - 48) * NV)
                              : (g_v + (ch - 96) * NV);
        float* d1 = d0 + NV;
        d0[v]     = c0;  d1[v]     = c1;
        d0[v + 8] = c2;  d1[v + 8] = c3;
    }
}

// ---------------------------------------------------------------------------
// Pass 2 (exact R10/R14-measured 32us version): per-channel attention,
// 4 outputs/thread, tile 4x8x64 (512 threads); div-free LDG.128 halo load.
// ---------------------------------------------------------------------------
template<int GRP>
__device__ __forceinline__ void attn_core(const float* __restrict__ sk,
                                          const float* __restrict__ sv,
                                          const float qs[4],
                                          const float qb[3][4],
                                          int rbase, int w0,
                                          float num[4], float den[4]) {
    #pragma unroll
    for (int kd = 0; kd < 3; kd++) {
        #pragma unroll
        for (int kh = 0; kh < 3; kh++) {
            const int rb = rbase + (kd * (TH + 2) + kh) * SROW + w0;
            const float4 ka = *(const float4*)(sk + rb);
            const float2 kc = *(const float2*)(sk + rb + 4);
            const float4 va = *(const float4*)(sv + rb);
            const float2 vc = *(const float2*)(sv + rb + 4);
            const float kk[6] = {ka.x, ka.y, ka.z, ka.w, kc.x, kc.y};
            const float vv[6] = {va.x, va.y, va.z, va.w, vc.x, vc.y};
            #pragma unroll
            for (int kw = 0; kw < 3; kw++) {
                const int sel = (GRP == 0) ? kw : ((GRP == 1) ? kd : kh);
                #pragma unroll
                for (int wi = 0; wi < 4; wi++) {
                    const float arg = fmaf(qs[wi], kk[wi + kw], qb[sel][wi]);
                    const float ex  = ex2f(arg);
                    den[wi] += ex;
                    num[wi] = fmaf(ex, vv[wi + kw], num[wi]);
                }
            }
        }
    }
}

__global__ __launch_bounds__(512, 3)
void attn_kernel(const float* __restrict__ rel_h,
                 const float* __restrict__ rel_w,
                 const float* __restrict__ rel_d,
                 float* __restrict__ out) {
    __shared__ float sk[NROWS * SROW];
    __shared__ float sv[NROWS * SROW];

    const int o  = blockIdx.z;
    const int d0 = blockIdx.x * TD;
    const int h0 = blockIdx.y * TH;
    const int tid = threadIdx.x + (threadIdx.y << 4) + (threadIdx.z << 7);

    const int w0 = threadIdx.x << 2;
    const int hl = threadIdx.y;
    const int dl = threadIdx.z;
    const int vox0 = ((d0 + dl) * HH + (h0 + hl)) * WW + w0;

    const float4 q4 = *(const float4*)(g_q + o * NV + vox0);
    const int grp = o >> 4, ci = o & 15;
    const float* rel = (grp == 0) ? (rel_d + ci * 3)
                     : (grp == 1) ? (rel_h + ci * 3)
                                  : (rel_w + ci * 3);
    const float b0 = rel[0], b1 = rel[1], b2 = rel[2];

    const float L2E = 1.4426950408889634f;
    float qs[4] = {q4.x * L2E, q4.y * L2E, q4.z * L2E, q4.w * L2E};
    float qb[3][4];
    #pragma unroll
    for (int wi = 0; wi < 4; wi++) {
        qb[0][wi] = qs[wi] * b0;
        qb[1][wi] = qs[wi] * b1;
        qb[2][wi] = qs[wi] * b2;
    }

    if (tid < NROWS * 2) {
        const int r = tid >> 1;
        const int c = (tid & 1) ? 65 : 0;
        sk[r * SROW + c] = 0.f;
        sv[r * SROW + c] = 0.f;
    }
    {
        const int cbase = o * NV;
        const int cx = (tid & 15) << 2;
        const int ry = tid >> 4;
        #pragma unroll
        for (int rr = 0; rr < 2; rr++) {
            const int r = ry + rr * 32;
            if (r < NROWS) {
                const int dd = r / (TH + 2);
                const int hh = r - dd * (TH + 2);
                const int d = d0 + dd - 1;
                const int h = h0 + hh - 1;
                float4 kq = {0.f, 0.f, 0.f, 0.f};
                float4 vq = {0.f, 0.f, 0.f, 0.f};
                if (((unsigned)d < DD) & ((unsigned)h < HH)) {
                    const int g = cbase + (d * HH + h) * WW + cx;
                    kq = *(const float4*)(g_k + g);
                    vq = *(const float4*)(g_v + g);
                }
                const int s = r * SROW + 1 + cx;
                sk[s + 0] = kq.x; sk[s + 1] = kq.y; sk[s + 2] = kq.z; sk[s + 3] = kq.w;
                sv[s + 0] = vq.x; sv[s + 1] = vq.y; sv[s + 2] = vq.z; sv[s + 3] = vq.w;
            }
        }
    }
    __syncthreads();

    const int rbase = (dl * (TH + 2) + hl) * SROW;

    float num[4] = {0.f, 0.f, 0.f, 0.f};
    float den[4] = {0.f, 0.f, 0.f, 0.f};

    if (grp == 0)      attn_core<0>(sk, sv, qs, qb, rbase, w0, num, den);
    else if (grp == 1) attn_core<1>(sk, sv, qs, qb, rbase, w0, num, den);
    else               attn_core<2>(sk, sv, qs, qb, rbase, w0, num, den);

    float4 r;
    r.x = num[0] * rcpf(den[0]);
    r.y = num[1] * rcpf(den[1]);
    r.z = num[2] * rcpf(den[2]);
    r.w = num[3] * rcpf(den[3]);
    *(float4*)(out + o * NV + vox0) = r;
}

extern "C" void kernel_launch(void* const* d_in, const int* in_sizes, int n_in,
                              void* d_out, int out_size) {
    const float* x     = (const float*)d_in[0];
    const float* Wq    = (const float*)d_in[1];
    const float* Wk    = (const float*)d_in[2];
    const float* Wv    = (const float*)d_in[3];
    const float* rel_h = (const float*)d_in[4];
    const float* rel_w = (const float*)d_in[5];
    const float* rel_d = (const float*)d_in[6];
    float* out = (float*)d_out;

    qkv_mma_kernel<<<NV / 128, 256>>>(x, Wq, Wk, Wv);

    dim3 g2(DD / TD, HH / TH, COUT);
    dim3 b2(16, TH, TD);
    attn_kernel<<<g2, b2>>>(rel_h, rel_w, rel_d, out);
}

// round 17
// speedup vs baseline: 1.5371x; 1.0388x over previous
#include <cuda_runtime.h>
#include <cuda_bf16.h>
#include <cstdint>

#define DD 24
#define HH 48
#define WW 64
#define NV (DD*HH*WW)        /* 73728 interior voxels */
#define CIN 32
#define COUT 48

#define TD 4
#define TH 8
#define SROW 68                        /* padded smem row stride (floats) */
#define NROWS ((TD+2)*(TH+2))          /* 60 */

// scratch (allocation-free rule: __device__ globals)
__device__ float g_q[COUT * NV];
__device__ float g_k[COUT * NV];
__device__ float g_v[COUT * NV];

__device__ __forceinline__ float ex2f(float x) {
    float y; asm("ex2.approx.ftz.f32 %0, %1;" : "=f"(y) : "f"(x)); return y;
}
__device__ __forceinline__ float rcpf(float x) {
    float y; asm("rcp.approx.ftz.f32 %0, %1;" : "=f"(y) : "f"(x)); return y;
}

// ---------------------------------------------------------------------------
// QKV via legacy tensor-core MMA (measured 15.2us, frozen):
// D[128 vox, 144 ch] = x_tile(128x32) . W^T, split-bf16 (AhBh+AhBl+AlBh).
// ---------------------------------------------------------------------------
#define XW 40   /* bf16 elems per smem row */

__device__ __forceinline__ void mma16816(float& c0, float& c1, float& c2, float& c3,
                                         uint32_t a0, uint32_t a1, uint32_t a2, uint32_t a3,
                                         uint32_t b0, uint32_t b1) {
    asm volatile(
        "mma.sync.aligned.m16n8k16.row.col.f32.bf16.bf16.f32 "
        "{%0,%1,%2,%3}, {%4,%5,%6,%7}, {%8,%9}, {%0,%1,%2,%3};"
        : "+f"(c0), "+f"(c1), "+f"(c2), "+f"(c3)
        : "r"(a0), "r"(a1), "r"(a2), "r"(a3), "r"(b0), "r"(b1));
}

__global__ __launch_bounds__(256)
void qkv_mma_kernel(const float* __restrict__ x,
                    const float* __restrict__ Wq,
                    const float* __restrict__ Wk,
                    const float* __restrict__ Wv) {
    __shared__ __nv_bfloat16 sxh[128 * XW];
    __shared__ __nv_bfloat16 sxl[128 * XW];
    __shared__ __nv_bfloat16 swh[144 * XW];
    __shared__ __nv_bfloat16 swl[144 * XW];

    const int t  = threadIdx.x;
    const int v0 = blockIdx.x * 128;

    #pragma unroll
    for (int i = 0; i < 16; i++) {
        const int idx = t + i * 256;
        const int c  = idx >> 7;
        const int vl = idx & 127;
        const float a = x[c * NV + v0 + vl];
        const __nv_bfloat16 h = __float2bfloat16(a);
        const float r = a - __bfloat162float(h);
        sxh[vl * XW + c] = h;
        sxl[vl * XW + c] = __float2bfloat16(r);
    }
    #pragma unroll
    for (int i = 0; i < 18; i++) {
        const int idx = t + i * 256;
        const int rrow = idx >> 5;
        const int c    = idx & 31;
        const float* wsrc = (rrow < 48) ? (Wq + rrow * CIN)
                          : (rrow < 96) ? (Wk + (rrow - 48) * CIN)
                                        : (Wv + (rrow - 96) * CIN);
        const float a = wsrc[c];
        const __nv_bfloat16 h = __float2bfloat16(a);
        const float r = a - __bfloat162float(h);
        swh[rrow * XW + c] = h;
        swl[rrow * XW + c] = __float2bfloat16(r);
    }
    __syncthreads();

    const int lane = t & 31;
    const int wid  = t >> 5;
    const int grp  = lane >> 2;
    const int qd   = lane & 3;
    const int vr   = wid * 16 + grp;
    const int v    = v0 + vr;

    uint32_t ah[2][4], al[2][4];
    #pragma unroll
    for (int ks = 0; ks < 2; ks++) {
        const int cb = qd * 2 + ks * 16;
        ah[ks][0] = *(const uint32_t*)&sxh[(vr)     * XW + cb];
        ah[ks][1] = *(const uint32_t*)&sxh[(vr + 8) * XW + cb];
        ah[ks][2] = *(const uint32_t*)&sxh[(vr)     * XW + cb + 8];
        ah[ks][3] = *(const uint32_t*)&sxh[(vr + 8) * XW + cb + 8];
        al[ks][0] = *(const uint32_t*)&sxl[(vr)     * XW + cb];
        al[ks][1] = *(const uint32_t*)&sxl[(vr + 8) * XW + cb];
        al[ks][2] = *(const uint32_t*)&sxl[(vr)     * XW + cb + 8];
        al[ks][3] = *(const uint32_t*)&sxl[(vr + 8) * XW + cb + 8];
    }

    #pragma unroll
    for (int nt = 0; nt < 18; nt++) {
        float c0 = 0.f, c1 = 0.f, c2 = 0.f, c3 = 0.f;
        const int nrow = nt * 8 + grp;
        #pragma unroll
        for (int ks = 0; ks < 2; ks++) {
            const int kb = qd * 2 + ks * 16;
            const uint32_t bh0 = *(const uint32_t*)&swh[nrow * XW + kb];
            const uint32_t bh1 = *(const uint32_t*)&swh[nrow * XW + kb + 8];
            const uint32_t bl0 = *(const uint32_t*)&swl[nrow * XW + kb];
            const uint32_t bl1 = *(const uint32_t*)&swl[nrow * XW + kb + 8];
            mma16816(c0, c1, c2, c3, ah[ks][0], ah[ks][1], ah[ks][2], ah[ks][3], bh0, bh1);
            mma16816(c0, c1, c2, c3, ah[ks][0], ah[ks][1], ah[ks][2], ah[ks][3], bl0, bl1);
            mma16816(c0, c1, c2, c3, al[ks][0], al[ks][1], al[ks][2], al[ks][3], bh0, bh1);
        }
        const int ch = nt * 8 + qd * 2;
        float* d0 = (ch < 48) ? (g_q + ch * NV)
                  : (ch < 96) ? (g_k + (ch - 48) * NV)
                              : (g_v + (ch - 96) * NV);
        float* d1 = d0 + NV;
        d0[v]     = c0;  d1[v]     = c1;
        d0[v + 8] = c2;  d1[v + 8] = c3;
    }
}

// ---------------------------------------------------------------------------
// Pass 2: per-channel attention, 8 outputs/thread (2h x 4w), 256 threads,
// tile 4x8x64. Shared h-window rows serve both h-outputs: LDS/output -33%.
// ---------------------------------------------------------------------------
template<int GRP>
__device__ __forceinline__ void attn_core(const float* __restrict__ sk,
                                          const float* __restrict__ sv,
                                          const float qs[2][4],
                                          const float qb[3][2][4],
                                          int tz, int ty2, int w0,
                                          float num[2][4], float den[2][4]) {
    #pragma unroll
    for (int kd = 0; kd < 3; kd++) {
        #pragma unroll
        for (int rr = 0; rr < 4; rr++) {
            const int rb = ((tz + kd) * (TH + 2) + (ty2 + rr)) * SROW + w0;
            const float4 ka = *(const float4*)(sk + rb);
            const float2 kc = *(const float2*)(sk + rb + 4);
            const float4 va = *(const float4*)(sv + rb);
            const float2 vc = *(const float2*)(sv + rb + 4);
            const float kk[6] = {ka.x, ka.y, ka.z, ka.w, kc.x, kc.y};
            const float vv[6] = {va.x, va.y, va.z, va.w, vc.x, vc.y};
            #pragma unroll
            for (int kw = 0; kw < 3; kw++) {
                if (rr < 3) {   // output 0: kh = rr
                    const int sel = (GRP == 0) ? kw : ((GRP == 1) ? kd : rr);
                    #pragma unroll
                    for (int wi = 0; wi < 4; wi++) {
                        const float arg = fmaf(qs[0][wi], kk[wi + kw], qb[sel][0][wi]);
                        const float ex  = ex2f(arg);
                        den[0][wi] += ex;
                        num[0][wi] = fmaf(ex, vv[wi + kw], num[0][wi]);
                    }
                }
                if (rr > 0) {   // output 1: kh = rr - 1
                    const int sel = (GRP == 0) ? kw : ((GRP == 1) ? kd : (rr - 1));
                    #pragma unroll
                    for (int wi = 0; wi < 4; wi++) {
                        const float arg = fmaf(qs[1][wi], kk[wi + kw], qb[sel][1][wi]);
                        const float ex  = ex2f(arg);
                        den[1][wi] += ex;
                        num[1][wi] = fmaf(ex, vv[wi + kw], num[1][wi]);
                    }
                }
            }
        }
    }
}

__global__ __launch_bounds__(256, 3)
void attn_kernel(const float* __restrict__ rel_h,
                 const float* __restrict__ rel_w,
                 const float* __restrict__ rel_d,
                 float* __restrict__ out) {
    __shared__ float sk[NROWS * SROW];
    __shared__ float sv[NROWS * SROW];

    const int o  = blockIdx.z;
    const int d0 = blockIdx.x * TD;
    const int h0 = blockIdx.y * TH;
    const int tid = threadIdx.x + (threadIdx.y << 4) + (threadIdx.z << 6);

    const int w0  = threadIdx.x << 2;        // 0..60
    const int ty2 = threadIdx.y << 1;        // h-pair base: 0,2,4,6
    const int tz  = threadIdx.z;             // 0..3

    // ---- hoisted q / bias loads ----
    const int vox0 = ((d0 + tz) * HH + (h0 + ty2)) * WW + w0;
    const int vox1 = vox0 + WW;

    const float4 q40 = *(const float4*)(g_q + o * NV + vox0);
    const float4 q41 = *(const float4*)(g_q + o * NV + vox1);
    const int grp = o >> 4, ci = o & 15;
    const float* rel = (grp == 0) ? (rel_d + ci * 3)
                     : (grp == 1) ? (rel_h + ci * 3)
                                  : (rel_w + ci * 3);
    const float b0 = rel[0], b1 = rel[1], b2 = rel[2];

    const float L2E = 1.4426950408889634f;
    float qs[2][4] = {{q40.x * L2E, q40.y * L2E, q40.z * L2E, q40.w * L2E},
                      {q41.x * L2E, q41.y * L2E, q41.z * L2E, q41.w * L2E}};
    float qb[3][2][4];
    #pragma unroll
    for (int oo = 0; oo < 2; oo++)
        #pragma unroll
        for (int wi = 0; wi < 4; wi++) {
            qb[0][oo][wi] = qs[oo][wi] * b0;
            qb[1][oo][wi] = qs[oo][wi] * b1;
            qb[2][oo][wi] = qs[oo][wi] * b2;
        }

    // ---- halo load (256 threads) ----
    if (tid < NROWS * 2) {
        const int r = tid >> 1;
        const int c = (tid & 1) ? 65 : 0;
        sk[r * SROW + c] = 0.f;
        sv[r * SROW + c] = 0.f;
    }
    {
        const int cbase = o * NV;
        const int cx = (tid & 15) << 2;
        const int ry = tid >> 4;               // 0..15
        #pragma unroll
        for (int rr = 0; rr < 4; rr++) {
            const int r = ry + rr * 16;
            if (r < NROWS) {
                const int dd = r / (TH + 2);
                const int hh = r - dd * (TH + 2);
                const int d = d0 + dd - 1;
                const int h = h0 + hh - 1;
                float4 kq = {0.f, 0.f, 0.f, 0.f};
                float4 vq = {0.f, 0.f, 0.f, 0.f};
                if (((unsigned)d < DD) & ((unsigned)h < HH)) {
                    const int g = cbase + (d * HH + h) * WW + cx;
                    kq = *(const float4*)(g_k + g);
                    vq = *(const float4*)(g_v + g);
                }
                const int s = r * SROW + 1 + cx;
                sk[s + 0] = kq.x; sk[s + 1] = kq.y; sk[s + 2] = kq.z; sk[s + 3] = kq.w;
                sv[s + 0] = vq.x; sv[s + 1] = vq.y; sv[s + 2] = vq.z; sv[s + 3] = vq.w;
            }
        }
    }
    __syncthreads();

    float num[2][4] = {{0.f, 0.f, 0.f, 0.f}, {0.f, 0.f, 0.f, 0.f}};
    float den[2][4] = {{0.f, 0.f, 0.f, 0.f}, {0.f, 0.f, 0.f, 0.f}};

    if (grp == 0)      attn_core<0>(sk, sv, qs, qb, tz, ty2, w0, num, den);
    else if (grp == 1) attn_core<1>(sk, sv, qs, qb, tz, ty2, w0, num, den);
    else               attn_core<2>(sk, sv, qs, qb, tz, ty2, w0, num, den);

    float4 r0, r1;
    r0.x = num[0][0] * rcpf(den[0][0]);
    r0.y = num[0][1] * rcpf(den[0][1]);
    r0.z = num[0][2] * rcpf(den[0][2]);
    r0.w = num[0][3] * rcpf(den[0][3]);
    r1.x = num[1][0] * rcpf(den[1][0]);
    r1.y = num[1][1] * rcpf(den[1][1]);
    r1.z = num[1][2] * rcpf(den[1][2]);
    r1.w = num[1][3] * rcpf(den[1][3]);
    *(float4*)(out + o * NV + vox0) = r0;
    *(float4*)(out + o * NV + vox1) = r1;
}

extern "C" void kernel_launch(void* const* d_in, const int* in_sizes, int n_in,
                              void* d_out, int out_size) {
    const float* x     = (const float*)d_in[0];
    const float* Wq    = (const float*)d_in[1];
    const float* Wk    = (const float*)d_in[2];
    const float* Wv    = (const float*)d_in[3];
    const float* rel_h = (const float*)d_in[4];
    const float* rel_w = (const float*)d_in[5];
    const float* rel_d = (const float*)d_in[6];
    float* out = (float*)d_out;

    qkv_mma_kernel<<<NV / 128, 256>>>(x, Wq, Wk, Wv);

    dim3 g2(DD / TD, HH / TH, COUT);
    dim3 b2(16, 4, 4);
    attn_kernel<<<g2, b2>>>(rel_h, rel_w, rel_d, out);
}